// round 3
// baseline (speedup 1.0000x reference)
#include <cuda_runtime.h>
#include <math.h>
#include <stdint.h>

// ---------------- problem constants ----------------
#define BB   64        // batches
#define DM   512       // d_model
#define NH   8         // heads
#define DKH  64        // d_k
#define DI   2048      // d_inner
#define NLAY 4
#define SS   12        // max type tokens per POI
#define REP_IDX 1
#define LMAX 385       // 1 + 32*12
#define LPAD 392

// ---------------- scratch (device globals; no runtime alloc) ----------------
__device__ int   g_seq_len[BB];
__device__ int   g_poi_idx[BB * LMAX];
__device__ int   g_tok_idx[BB * LMAX];
__device__ float g_x [BB * LMAX * DM];
__device__ float g_q [BB * LMAX * DM];
__device__ float g_k [BB * LMAX * DM];
__device__ float g_v [BB * LMAX * DM];
__device__ float g_ao[BB * LMAX * DM];
__device__ float g_y [BB * LMAX * DM];
__device__ float g_h [BB * LMAX * DI];

// ---------------- pack: replicate pack_indices on device ----------------
__global__ void pack_kernel(const int* __restrict__ npl,
                            const int* __restrict__ ttn, int L) {
    int b = threadIdx.x;
    if (b >= BB) return;
    int start = 0;
    for (int i = 0; i < b; i++) start += npl[i];
    int end = start + npl[b];
    int pos = 1;  // slot 0 = [REP]
    for (int p = start; p < end; p++) {
        int t = ttn[p];
        for (int u = 0; u < t && pos < L; u++) {
            g_poi_idx[b * L + pos] = p;
            g_tok_idx[b * L + pos] = u;
            pos++;
        }
    }
    g_seq_len[b] = pos;
}

// ---------------- block reduce (128 threads) ----------------
__device__ __forceinline__ void block_reduce2_128(float& s, float& sq) {
    #pragma unroll
    for (int o = 16; o > 0; o >>= 1) {
        s  += __shfl_xor_sync(0xFFFFFFFFu, s,  o);
        sq += __shfl_xor_sync(0xFFFFFFFFu, sq, o);
    }
    __shared__ float rs[4], rq[4];
    int w = threadIdx.x >> 5, ln = threadIdx.x & 31;
    if (ln == 0) { rs[w] = s; rq[w] = sq; }
    __syncthreads();
    s  = rs[0] + rs[1] + rs[2] + rs[3];
    sq = rq[0] + rq[1] + rq[2] + rq[3];
}

// sinusoid positional table element (t < 12, d < 512)
__device__ __forceinline__ float postab(int t, int d) {
    int i2 = d & ~1;
    float f = powf(10000.0f, -(float)i2 / (float)DM);
    float ang = (float)t * f;
    return (d & 1) ? cosf(ang) : sinf(ang);
}

// ---------------- embed + final LN ----------------
__global__ __launch_bounds__(128) void embed_ln_kernel(
    const int* __restrict__ poi_type, const float* __restrict__ loc_emb,
    const float* __restrict__ emb, const float* __restrict__ lnf_g,
    const float* __restrict__ lnf_b, int L) {
    int row = blockIdx.x;           // b*L + l
    int b = row / L, l = row - b * L;
    int tid = threadIdx.x;
    int d0 = tid * 4;
    float v[4];
    int sl = g_seq_len[b];
    if (l == 0) {
        #pragma unroll
        for (int i = 0; i < 4; i++) v[i] = emb[REP_IDX * DM + d0 + i];
    } else if (l < sl) {
        int p = g_poi_idx[b * L + l];
        int t = g_tok_idx[b * L + l];
        int tok = poi_type[p * SS + t];
        #pragma unroll
        for (int i = 0; i < 4; i++) {
            int d = d0 + i;
            v[i] = emb[tok * DM + d] + postab(t, d) + loc_emb[p * DM + d];
        }
    } else {
        #pragma unroll
        for (int i = 0; i < 4; i++) v[i] = 0.0f;
    }
    float s = v[0] + v[1] + v[2] + v[3];
    float sq = v[0]*v[0] + v[1]*v[1] + v[2]*v[2] + v[3]*v[3];
    block_reduce2_128(s, sq);
    float mean = s * (1.0f / DM);
    float var  = sq * (1.0f / DM) - mean * mean;
    float r = rsqrtf(var + 1e-6f);
    float4 o;
    o.x = lnf_g[d0+0] * (v[0]-mean) * r + lnf_b[d0+0];
    o.y = lnf_g[d0+1] * (v[1]-mean) * r + lnf_b[d0+1];
    o.z = lnf_g[d0+2] * (v[2]-mean) * r + lnf_b[d0+2];
    o.w = lnf_g[d0+3] * (v[3]-mean) * r + lnf_b[d0+3];
    *(float4*)(g_x + (size_t)row * DM + d0) = o;
}

// ---------------- residual + LN (x = LN(x + y)) ----------------
__global__ __launch_bounds__(128) void resid_ln_kernel(
    float* __restrict__ x, const float* __restrict__ y,
    const float* __restrict__ g, const float* __restrict__ bb) {
    size_t base = (size_t)blockIdx.x * DM + threadIdx.x * 4;
    float4 xv = *(float4*)(x + base);
    float4 yv = *(const float4*)(y + base);
    float v[4] = { xv.x + yv.x, xv.y + yv.y, xv.z + yv.z, xv.w + yv.w };
    float s = v[0] + v[1] + v[2] + v[3];
    float sq = v[0]*v[0] + v[1]*v[1] + v[2]*v[2] + v[3]*v[3];
    block_reduce2_128(s, sq);
    float mean = s * (1.0f / DM);
    float var  = sq * (1.0f / DM) - mean * mean;
    float r = rsqrtf(var + 1e-6f);
    int d0 = threadIdx.x * 4;
    float4 o;
    o.x = g[d0+0] * (v[0]-mean) * r + bb[d0+0];
    o.y = g[d0+1] * (v[1]-mean) * r + bb[d0+1];
    o.z = g[d0+2] * (v[2]-mean) * r + bb[d0+2];
    o.w = g[d0+3] * (v[3]-mean) * r + bb[d0+3];
    *(float4*)(x + base) = o;
}

// ---------------- SGEMM: C[M,N] = A[M,K] @ W[K,N] (+bias)(+relu) ----------------
// 128x128 tile, BK=8, 256 threads, 8x8 microtile, double buffered.
__global__ __launch_bounds__(256, 2) void sgemm_kernel(
    const float* __restrict__ A, const float* __restrict__ W,
    const float* __restrict__ bias, float* __restrict__ C,
    int M, int N, int K, int do_relu) {
    __shared__ float As[2][8][128];
    __shared__ float Bs[2][8][128];
    const int tid = threadIdx.x;
    const int row0 = blockIdx.y * 128, col0 = blockIdx.x * 128;
    const int tx = tid & 15, ty = tid >> 4;
    const int a_row = tid >> 1, a_k = (tid & 1) * 4;
    const int b_k = tid >> 5, b_col = (tid & 31) * 4;

    float acc[8][8];
    #pragma unroll
    for (int i = 0; i < 8; i++)
        #pragma unroll
        for (int j = 0; j < 8; j++) acc[i][j] = 0.0f;

    auto load_tiles = [&](int k0, int bufi) {
        float4 av = make_float4(0.f, 0.f, 0.f, 0.f);
        int grow = row0 + a_row;
        if (grow < M) av = *(const float4*)(A + (size_t)grow * K + k0 + a_k);
        As[bufi][a_k + 0][a_row] = av.x;
        As[bufi][a_k + 1][a_row] = av.y;
        As[bufi][a_k + 2][a_row] = av.z;
        As[bufi][a_k + 3][a_row] = av.w;
        float4 bv = *(const float4*)(W + (size_t)(k0 + b_k) * N + col0 + b_col);
        *(float4*)&Bs[bufi][b_k][b_col] = bv;
    };

    load_tiles(0, 0);
    __syncthreads();
    int buf = 0;
    for (int k0 = 0; k0 < K; k0 += 8) {
        int nb = buf ^ 1;
        if (k0 + 8 < K) load_tiles(k0 + 8, nb);
        #pragma unroll
        for (int kk = 0; kk < 8; kk++) {
            float af[8], bf[8];
            #pragma unroll
            for (int i = 0; i < 4; i++) {
                af[i]     = As[buf][kk][ty * 4 + i];
                af[4 + i] = As[buf][kk][64 + ty * 4 + i];
            }
            #pragma unroll
            for (int j = 0; j < 4; j++) {
                bf[j]     = Bs[buf][kk][tx * 4 + j];
                bf[4 + j] = Bs[buf][kk][64 + tx * 4 + j];
            }
            #pragma unroll
            for (int i = 0; i < 8; i++)
                #pragma unroll
                for (int j = 0; j < 8; j++)
                    acc[i][j] += af[i] * bf[j];
        }
        __syncthreads();
        buf = nb;
    }

    #pragma unroll
    for (int i = 0; i < 8; i++) {
        int r = row0 + ((i < 4) ? (ty * 4 + i) : (64 + ty * 4 + (i - 4)));
        if (r >= M) continue;
        #pragma unroll
        for (int jb = 0; jb < 2; jb++) {
            int c = col0 + ((jb == 0) ? (tx * 4) : (64 + tx * 4));
            float4 o;
            o.x = acc[i][jb * 4 + 0];
            o.y = acc[i][jb * 4 + 1];
            o.z = acc[i][jb * 4 + 2];
            o.w = acc[i][jb * 4 + 3];
            if (bias) {
                o.x += bias[c + 0]; o.y += bias[c + 1];
                o.z += bias[c + 2]; o.w += bias[c + 3];
            }
            if (do_relu) {
                o.x = fmaxf(o.x, 0.f); o.y = fmaxf(o.y, 0.f);
                o.z = fmaxf(o.z, 0.f); o.w = fmaxf(o.w, 0.f);
            }
            *(float4*)(C + (size_t)r * N + c) = o;
        }
    }
}

// ---------------- attention: one block per (b,h), one warp per query ----------------
__global__ __launch_bounds__(256) void attn_kernel(
    const float* __restrict__ Q, const float* __restrict__ K,
    const float* __restrict__ V, float* __restrict__ O, int L) {
    int b = blockIdx.x, h = blockIdx.y;
    int w = threadIdx.x >> 5, lane = threadIdx.x & 31;
    __shared__ float sc[8][LPAD];
    __shared__ float qs[8][DKH];
    int sl = g_seq_len[b];
    size_t base = ((size_t)b * L) * DM + h * DKH;

    for (int i = w; i < L; i += 8) {
        const float* qrow = Q + base + (size_t)i * DM;
        qs[w][lane]      = qrow[lane];
        qs[w][32 + lane] = qrow[32 + lane];
        __syncwarp();
        // phase 1: scores + max
        float m = -INFINITY;
        for (int j = lane; j < L; j += 32) {
            float s;
            if (j < sl) {
                const float* krow = K + base + (size_t)j * DM;
                float dot = 0.f;
                #pragma unroll
                for (int d = 0; d < DKH; d += 4) {
                    float4 kv = *(const float4*)(krow + d);
                    dot += qs[w][d+0]*kv.x + qs[w][d+1]*kv.y
                         + qs[w][d+2]*kv.z + qs[w][d+3]*kv.w;
                }
                s = dot * 0.125f;
            } else {
                s = -1e9f;
            }
            sc[w][j] = s;
            m = fmaxf(m, s);
        }
        #pragma unroll
        for (int o = 16; o > 0; o >>= 1) m = fmaxf(m, __shfl_xor_sync(0xFFFFFFFFu, m, o));
        // phase 2: exp + sum
        float sum = 0.f;
        for (int j = lane; j < L; j += 32) {
            float e = expf(sc[w][j] - m);
            sc[w][j] = e;
            sum += e;
        }
        #pragma unroll
        for (int o = 16; o > 0; o >>= 1) sum += __shfl_xor_sync(0xFFFFFFFFu, sum, o);
        float inv = 1.0f / sum;
        __syncwarp();
        // phase 3: O = P @ V   (lane owns dims lane, lane+32)
        float a0 = 0.f, a1 = 0.f;
        int d0 = lane, d1 = 32 + lane;
        int j = 0;
        for (; j + 4 <= L; j += 4) {
            float p0 = sc[w][j], p1 = sc[w][j+1], p2 = sc[w][j+2], p3 = sc[w][j+3];
            const float* v0 = V + base + (size_t)(j    ) * DM;
            const float* v1 = V + base + (size_t)(j + 1) * DM;
            const float* v2 = V + base + (size_t)(j + 2) * DM;
            const float* v3 = V + base + (size_t)(j + 3) * DM;
            a0 += p0 * v0[d0] + p1 * v1[d0] + p2 * v2[d0] + p3 * v3[d0];
            a1 += p0 * v0[d1] + p1 * v1[d1] + p2 * v2[d1] + p3 * v3[d1];
        }
        for (; j < L; j++) {
            float p = sc[w][j];
            const float* vr = V + base + (size_t)j * DM;
            a0 += p * vr[d0];
            a1 += p * vr[d1];
        }
        float* orow = O + base + (size_t)i * DM;
        orow[d0] = a0 * inv;
        orow[d1] = a1 * inv;
        __syncwarp();
    }
}

// ---------------- writeout: d_out = [x (B*L*512), attn_mask (B*L)] ----------------
__global__ void writeout_kernel(float* __restrict__ out, int L, int with_mask) {
    int idx = blockIdx.x * blockDim.x + threadIdx.x;
    int total = BB * L * DM;
    if (idx < total) out[idx] = g_x[idx];
    if (with_mask && idx < BB * L) {
        int b = idx / L, l = idx - b * L;
        out[total + idx] = (l < g_seq_len[b]) ? 1.0f : 0.0f;
    }
}

// ---------------- host launcher ----------------
extern "C" void kernel_launch(void* const* d_in, const int* in_sizes, int n_in,
                              void* d_out, int out_size) {
    const int*   poi_type = (const int*)  d_in[0];
    const float* loc_emb  = (const float*)d_in[1];
    const int*   npl      = (const int*)  d_in[2];
    const int*   ttn      = (const int*)  d_in[3];
    const float* emb      = (const float*)d_in[4];
    const float* Wq       = (const float*)d_in[5];
    const float* Wk       = (const float*)d_in[6];
    const float* Wv       = (const float*)d_in[7];
    const float* Wo       = (const float*)d_in[8];
    const float* bo       = (const float*)d_in[9];
    const float* ln1_g    = (const float*)d_in[10];
    const float* ln1_b    = (const float*)d_in[11];
    const float* W1       = (const float*)d_in[12];
    const float* b1       = (const float*)d_in[13];
    const float* W2       = (const float*)d_in[14];
    const float* b2       = (const float*)d_in[15];
    const float* ln2_g    = (const float*)d_in[16];
    const float* ln2_b    = (const float*)d_in[17];
    const float* lnf_g    = (const float*)d_in[18];
    const float* lnf_b    = (const float*)d_in[19];

    int L, with_mask;
    if (out_size % (BB * (DM + 1)) == 0) { L = out_size / (BB * (DM + 1)); with_mask = 1; }
    else                                 { L = out_size / (BB * DM);        with_mask = 0; }
    const int M = BB * L;

    float *x, *q, *k, *v, *ao, *y, *hbuf;
    cudaGetSymbolAddress((void**)&x,    g_x);
    cudaGetSymbolAddress((void**)&q,    g_q);
    cudaGetSymbolAddress((void**)&k,    g_k);
    cudaGetSymbolAddress((void**)&v,    g_v);
    cudaGetSymbolAddress((void**)&ao,   g_ao);
    cudaGetSymbolAddress((void**)&y,    g_y);
    cudaGetSymbolAddress((void**)&hbuf, g_h);

    pack_kernel<<<1, 64>>>(npl, ttn, L);
    embed_ln_kernel<<<M, 128>>>(poi_type, loc_emb, emb, lnf_g, lnf_b, L);

    dim3 g512((DM + 127) / 128, (M + 127) / 128);
    dim3 g2048((DI + 127) / 128, (M + 127) / 128);
    dim3 gattn(BB, NH);

    for (int l = 0; l < NLAY; l++) {
        const float* wq = Wq + (size_t)l * DM * DM;
        const float* wk = Wk + (size_t)l * DM * DM;
        const float* wv = Wv + (size_t)l * DM * DM;
        const float* wo = Wo + (size_t)l * DM * DM;
        const float* w1 = W1 + (size_t)l * DM * DI;
        const float* w2 = W2 + (size_t)l * DI * DM;

        sgemm_kernel<<<g512, 256>>>(x, wq, nullptr, q, M, DM, DM, 0);
        sgemm_kernel<<<g512, 256>>>(x, wk, nullptr, k, M, DM, DM, 0);
        sgemm_kernel<<<g512, 256>>>(x, wv, nullptr, v, M, DM, DM, 0);
        attn_kernel<<<gattn, 256>>>(q, k, v, ao, L);
        sgemm_kernel<<<g512, 256>>>(ao, wo, bo + (size_t)l * DM, y, M, DM, DM, 0);
        resid_ln_kernel<<<M, 128>>>(x, y, ln1_g + (size_t)l * DM, ln1_b + (size_t)l * DM);
        sgemm_kernel<<<g2048, 256>>>(x, w1, b1 + (size_t)l * DI, hbuf, M, DI, DM, 1);
        sgemm_kernel<<<g512, 256>>>(hbuf, w2, b2 + (size_t)l * DM, y, M, DM, DI, 0);
        resid_ln_kernel<<<M, 128>>>(x, y, ln2_g + (size_t)l * DM, ln2_b + (size_t)l * DM);
    }

    int n_out = BB * L * DM + (with_mask ? BB * L : 0);
    writeout_kernel<<<(n_out + 255) / 256, 256>>>((float*)d_out, L, with_mask);
}

// round 4
// speedup vs baseline: 2.1580x; 2.1580x over previous
#include <cuda_runtime.h>
#include <math.h>
#include <stdint.h>

// ---------------- problem constants ----------------
#define BB   64        // batches
#define DM   512       // d_model
#define NH   8         // heads
#define DKH  64        // d_k
#define DI   2048      // d_inner
#define NLAY 4
#define SS   12        // max type tokens per POI
#define REP_IDX 1
#define LMAX 385       // 1 + 32*12
#define LPAD 392

// ---------------- scratch (device globals; no runtime alloc) ----------------
__device__ int   g_seq_len[BB];
__device__ int   g_poi_idx[BB * LMAX];
__device__ int   g_tok_idx[BB * LMAX];
__device__ float g_x [BB * LMAX * DM];
__device__ float g_q [BB * LMAX * DM];
__device__ float g_k [BB * LMAX * DM];
__device__ float g_v [BB * LMAX * DM];
__device__ float g_ao[BB * LMAX * DM];
__device__ float g_y [BB * LMAX * DM];
__device__ float g_h [BB * LMAX * DI];

// ---------------- pack: replicate pack_indices on device ----------------
__global__ void pack_kernel(const int* __restrict__ npl,
                            const int* __restrict__ ttn, int L) {
    int b = threadIdx.x;
    if (b >= BB) return;
    int start = 0;
    for (int i = 0; i < b; i++) start += npl[i];
    int end = start + npl[b];
    int pos = 1;  // slot 0 = [REP]
    for (int p = start; p < end; p++) {
        int t = ttn[p];
        for (int u = 0; u < t && pos < L; u++) {
            g_poi_idx[b * L + pos] = p;
            g_tok_idx[b * L + pos] = u;
            pos++;
        }
    }
    g_seq_len[b] = pos;
}

// ---------------- block reduce (128 threads) ----------------
__device__ __forceinline__ void block_reduce2_128(float& s, float& sq) {
    #pragma unroll
    for (int o = 16; o > 0; o >>= 1) {
        s  += __shfl_xor_sync(0xFFFFFFFFu, s,  o);
        sq += __shfl_xor_sync(0xFFFFFFFFu, sq, o);
    }
    __shared__ float rs[4], rq[4];
    int w = threadIdx.x >> 5, ln = threadIdx.x & 31;
    if (ln == 0) { rs[w] = s; rq[w] = sq; }
    __syncthreads();
    s  = rs[0] + rs[1] + rs[2] + rs[3];
    sq = rq[0] + rq[1] + rq[2] + rq[3];
}

// sinusoid positional table element (t < 12, d < 512)
__device__ __forceinline__ float postab(int t, int d) {
    int i2 = d & ~1;
    float f = powf(10000.0f, -(float)i2 / (float)DM);
    float ang = (float)t * f;
    return (d & 1) ? cosf(ang) : sinf(ang);
}

// ---------------- embed + final LN ----------------
__global__ __launch_bounds__(128) void embed_ln_kernel(
    const int* __restrict__ poi_type, const float* __restrict__ loc_emb,
    const float* __restrict__ emb, const float* __restrict__ lnf_g,
    const float* __restrict__ lnf_b, int L) {
    int row = blockIdx.x;           // b*L + l
    int b = row / L, l = row - b * L;
    int tid = threadIdx.x;
    int d0 = tid * 4;
    float v[4];
    int sl = g_seq_len[b];
    if (l == 0) {
        #pragma unroll
        for (int i = 0; i < 4; i++) v[i] = emb[REP_IDX * DM + d0 + i];
    } else if (l < sl) {
        int p = g_poi_idx[b * L + l];
        int t = g_tok_idx[b * L + l];
        int tok = poi_type[p * SS + t];
        #pragma unroll
        for (int i = 0; i < 4; i++) {
            int d = d0 + i;
            v[i] = emb[tok * DM + d] + postab(t, d) + loc_emb[p * DM + d];
        }
    } else {
        #pragma unroll
        for (int i = 0; i < 4; i++) v[i] = 0.0f;
    }
    float s = v[0] + v[1] + v[2] + v[3];
    float sq = v[0]*v[0] + v[1]*v[1] + v[2]*v[2] + v[3]*v[3];
    block_reduce2_128(s, sq);
    float mean = s * (1.0f / DM);
    float var  = sq * (1.0f / DM) - mean * mean;
    float r = rsqrtf(var + 1e-6f);
    float4 o;
    o.x = lnf_g[d0+0] * (v[0]-mean) * r + lnf_b[d0+0];
    o.y = lnf_g[d0+1] * (v[1]-mean) * r + lnf_b[d0+1];
    o.z = lnf_g[d0+2] * (v[2]-mean) * r + lnf_b[d0+2];
    o.w = lnf_g[d0+3] * (v[3]-mean) * r + lnf_b[d0+3];
    *(float4*)(g_x + (size_t)row * DM + d0) = o;
}

// ---------------- residual + LN (x = LN(x + y)) ----------------
__global__ __launch_bounds__(128) void resid_ln_kernel(
    float* __restrict__ x, const float* __restrict__ y,
    const float* __restrict__ g, const float* __restrict__ bb) {
    size_t base = (size_t)blockIdx.x * DM + threadIdx.x * 4;
    float4 xv = *(float4*)(x + base);
    float4 yv = *(const float4*)(y + base);
    float v[4] = { xv.x + yv.x, xv.y + yv.y, xv.z + yv.z, xv.w + yv.w };
    float s = v[0] + v[1] + v[2] + v[3];
    float sq = v[0]*v[0] + v[1]*v[1] + v[2]*v[2] + v[3]*v[3];
    block_reduce2_128(s, sq);
    float mean = s * (1.0f / DM);
    float var  = sq * (1.0f / DM) - mean * mean;
    float r = rsqrtf(var + 1e-6f);
    int d0 = threadIdx.x * 4;
    float4 o;
    o.x = g[d0+0] * (v[0]-mean) * r + bb[d0+0];
    o.y = g[d0+1] * (v[1]-mean) * r + bb[d0+1];
    o.z = g[d0+2] * (v[2]-mean) * r + bb[d0+2];
    o.w = g[d0+3] * (v[3]-mean) * r + bb[d0+3];
    *(float4*)(x + base) = o;
}

// ---------------- tf32 helpers ----------------
__device__ __forceinline__ float f2tf(float x) {
    uint32_t u;
    asm("cvt.rna.tf32.f32 %0, %1;" : "=r"(u) : "f"(x));
    return __uint_as_float(u);
}

__device__ __forceinline__ void mma1688(float* c, const uint32_t* a, const uint32_t* b) {
    asm volatile(
        "mma.sync.aligned.m16n8k8.row.col.f32.tf32.tf32.f32 "
        "{%0,%1,%2,%3}, {%4,%5,%6,%7}, {%8,%9}, {%0,%1,%2,%3};"
        : "+f"(c[0]), "+f"(c[1]), "+f"(c[2]), "+f"(c[3])
        : "r"(a[0]), "r"(a[1]), "r"(a[2]), "r"(a[3]),
          "r"(b[0]), "r"(b[1]));
}

// ---------------- tf32 tensor-core GEMM ----------------
// C[M,N] = A[M,K] @ W[K,N] (+bias)(+relu)
// 128x128 block tile, BK=16 double-buffered, 8 warps (4x2), warp tile 32x64.
#define GSTR 136
__global__ __launch_bounds__(256, 2) void mma_gemm_kernel(
    const float* __restrict__ A, const float* __restrict__ W,
    const float* __restrict__ bias, float* __restrict__ C,
    int M, int N, int K, int do_relu) {
    __shared__ float As[2][16][GSTR];   // [k][m]
    __shared__ float Bs[2][16][GSTR];   // [k][n]
    const int tid  = threadIdx.x;
    const int wid  = tid >> 5, lane = tid & 31;
    const int wm   = (wid & 3) * 32;
    const int wn   = (wid >> 2) * 64;
    const int row0 = blockIdx.y * 128, col0 = blockIdx.x * 128;

    const int a_row = tid >> 1, a_k = (tid & 1) * 8;
    const int b_k   = tid >> 5, b_n = (tid & 31) * 4;

    float acc[2][8][4];
    #pragma unroll
    for (int mt = 0; mt < 2; mt++)
        #pragma unroll
        for (int nt = 0; nt < 8; nt++)
            #pragma unroll
            for (int i = 0; i < 4; i++) acc[mt][nt][i] = 0.0f;

    float4 sa0, sa1, sb0, sb1;

    auto gload = [&](int k0) {
        int gr = row0 + a_row;
        if (gr < M) {
            const float* ap = A + (size_t)gr * K + k0 + a_k;
            sa0 = *(const float4*)(ap);
            sa1 = *(const float4*)(ap + 4);
        } else {
            sa0 = make_float4(0.f,0.f,0.f,0.f);
            sa1 = sa0;
        }
        sb0 = *(const float4*)(W + (size_t)(k0 + b_k)     * N + col0 + b_n);
        sb1 = *(const float4*)(W + (size_t)(k0 + b_k + 8) * N + col0 + b_n);
    };
    auto sstore = [&](int bf) {
        As[bf][a_k+0][a_row] = f2tf(sa0.x);
        As[bf][a_k+1][a_row] = f2tf(sa0.y);
        As[bf][a_k+2][a_row] = f2tf(sa0.z);
        As[bf][a_k+3][a_row] = f2tf(sa0.w);
        As[bf][a_k+4][a_row] = f2tf(sa1.x);
        As[bf][a_k+5][a_row] = f2tf(sa1.y);
        As[bf][a_k+6][a_row] = f2tf(sa1.z);
        As[bf][a_k+7][a_row] = f2tf(sa1.w);
        Bs[bf][b_k][b_n+0] = f2tf(sb0.x);
        Bs[bf][b_k][b_n+1] = f2tf(sb0.y);
        Bs[bf][b_k][b_n+2] = f2tf(sb0.z);
        Bs[bf][b_k][b_n+3] = f2tf(sb0.w);
        Bs[bf][b_k+8][b_n+0] = f2tf(sb1.x);
        Bs[bf][b_k+8][b_n+1] = f2tf(sb1.y);
        Bs[bf][b_k+8][b_n+2] = f2tf(sb1.z);
        Bs[bf][b_k+8][b_n+3] = f2tf(sb1.w);
    };

    gload(0);
    sstore(0);
    __syncthreads();

    const int r = lane >> 2, c = lane & 3;
    int buf = 0;
    for (int k0 = 0; k0 < K; k0 += 16) {
        bool nxt = (k0 + 16) < K;
        if (nxt) gload(k0 + 16);
        #pragma unroll
        for (int ks = 0; ks < 16; ks += 8) {
            uint32_t af[2][4], bfr[8][2];
            #pragma unroll
            for (int mt = 0; mt < 2; mt++) {
                int mb = wm + mt * 16 + r;
                af[mt][0] = __float_as_uint(As[buf][ks + c    ][mb    ]);
                af[mt][1] = __float_as_uint(As[buf][ks + c    ][mb + 8]);
                af[mt][2] = __float_as_uint(As[buf][ks + c + 4][mb    ]);
                af[mt][3] = __float_as_uint(As[buf][ks + c + 4][mb + 8]);
            }
            #pragma unroll
            for (int nt = 0; nt < 8; nt++) {
                int nb = wn + nt * 8 + r;
                bfr[nt][0] = __float_as_uint(Bs[buf][ks + c    ][nb]);
                bfr[nt][1] = __float_as_uint(Bs[buf][ks + c + 4][nb]);
            }
            #pragma unroll
            for (int mt = 0; mt < 2; mt++)
                #pragma unroll
                for (int nt = 0; nt < 8; nt++)
                    mma1688(acc[mt][nt], af[mt], bfr[nt]);
        }
        if (nxt) sstore(buf ^ 1);
        __syncthreads();
        buf ^= 1;
    }

    // epilogue
    #pragma unroll
    for (int mt = 0; mt < 2; mt++) {
        int rrow = row0 + wm + mt * 16 + (lane >> 2);
        #pragma unroll
        for (int nt = 0; nt < 8; nt++) {
            int ccol = col0 + wn + nt * 8 + (lane & 3) * 2;
            float2 v0 = make_float2(acc[mt][nt][0], acc[mt][nt][1]);
            float2 v1 = make_float2(acc[mt][nt][2], acc[mt][nt][3]);
            if (bias) {
                float b0 = bias[ccol], b1 = bias[ccol + 1];
                v0.x += b0; v0.y += b1;
                v1.x += b0; v1.y += b1;
            }
            if (do_relu) {
                v0.x = fmaxf(v0.x, 0.f); v0.y = fmaxf(v0.y, 0.f);
                v1.x = fmaxf(v1.x, 0.f); v1.y = fmaxf(v1.y, 0.f);
            }
            if (rrow < M)     *(float2*)(C + (size_t)rrow     * N + ccol) = v0;
            if (rrow + 8 < M) *(float2*)(C + (size_t)(rrow+8) * N + ccol) = v1;
        }
    }
}

// ---------------- attention: block per (b,h), K staged in smem tiles ----------------
#define KT 32
#define KSTR 68
__global__ __launch_bounds__(256) void attn_kernel(
    const float* __restrict__ Q, const float* __restrict__ K,
    const float* __restrict__ V, float* __restrict__ O, int L) {
    __shared__ float sc[8][LPAD];     // one score row per warp
    __shared__ float kt[KT][KSTR];    // K tile, stride 68 (16B-aligned, phase-conflict-free)
    int b = blockIdx.x, h = blockIdx.y;
    int tid = threadIdx.x;
    int w = tid >> 5, lane = tid & 31;
    int sl = g_seq_len[b];
    size_t base = ((size_t)b * L) * DM + h * DKH;

    int nw = (L + 7) / 8;
    for (int iw = 0; iw < nw; iw++) {
        int i = iw * 8 + w;
        bool act = (i < L);
        float4 qv[16];
        if (act) {
            const float4* qp = (const float4*)(Q + base + (size_t)i * DM);
            #pragma unroll
            for (int d = 0; d < 16; d++) qv[d] = qp[d];
        }
        float m = -3.0e38f;
        for (int jt = 0; jt < L; jt += KT) {
            __syncthreads();
            {
                int kr = tid >> 3, kc = (tid & 7) * 8;
                int gj = jt + kr;
                if (gj < L) {
                    const float4* kp = (const float4*)(K + base + (size_t)gj * DM + kc);
                    *(float4*)&kt[kr][kc]     = kp[0];
                    *(float4*)&kt[kr][kc + 4] = kp[1];
                }
            }
            __syncthreads();
            if (act) {
                int j = jt + lane;
                if (j < L) {
                    float s = -1e9f;
                    if (j < sl) {
                        float dot = 0.f;
                        #pragma unroll
                        for (int d = 0; d < 16; d++) {
                            float4 kv = *(const float4*)&kt[lane][d * 4];
                            dot += qv[d].x * kv.x + qv[d].y * kv.y
                                 + qv[d].z * kv.z + qv[d].w * kv.w;
                        }
                        s = dot * 0.125f;
                    }
                    sc[w][j] = s;
                    m = fmaxf(m, s);
                }
            }
        }
        if (act) {
            #pragma unroll
            for (int o = 16; o > 0; o >>= 1)
                m = fmaxf(m, __shfl_xor_sync(0xFFFFFFFFu, m, o));
            float sum = 0.f;
            for (int j = lane; j < L; j += 32) {
                float e = expf(sc[w][j] - m);
                sc[w][j] = e;
                sum += e;
            }
            #pragma unroll
            for (int o = 16; o > 0; o >>= 1)
                sum += __shfl_xor_sync(0xFFFFFFFFu, sum, o);
            float inv = 1.0f / sum;
            __syncwarp();
            // PV: lane owns dims (2*lane, 2*lane+1); coalesced float2 V loads
            float ax = 0.f, ay = 0.f;
            const float* vp = V + base + 2 * lane;
            int j = 0;
            #pragma unroll 4
            for (; j < L; j++) {
                float2 vv = *(const float2*)(vp + (size_t)j * DM);
                float p = sc[w][j];
                ax += p * vv.x;
                ay += p * vv.y;
            }
            float2 o2 = make_float2(ax * inv, ay * inv);
            *(float2*)(O + base + (size_t)i * DM + 2 * lane) = o2;
        }
    }
}

// ---------------- writeout: d_out = [x (B*L*512), attn_mask (B*L)] ----------------
__global__ void writeout_kernel(float* __restrict__ out, int L, int with_mask) {
    int idx = blockIdx.x * blockDim.x + threadIdx.x;
    int total = BB * L * DM;
    if (idx < total) out[idx] = g_x[idx];
    if (with_mask && idx < BB * L) {
        int b = idx / L, l = idx - b * L;
        out[total + idx] = (l < g_seq_len[b]) ? 1.0f : 0.0f;
    }
}

// ---------------- host launcher ----------------
extern "C" void kernel_launch(void* const* d_in, const int* in_sizes, int n_in,
                              void* d_out, int out_size) {
    const int*   poi_type = (const int*)  d_in[0];
    const float* loc_emb  = (const float*)d_in[1];
    const int*   npl      = (const int*)  d_in[2];
    const int*   ttn      = (const int*)  d_in[3];
    const float* emb      = (const float*)d_in[4];
    const float* Wq       = (const float*)d_in[5];
    const float* Wk       = (const float*)d_in[6];
    const float* Wv       = (const float*)d_in[7];
    const float* Wo       = (const float*)d_in[8];
    const float* bo       = (const float*)d_in[9];
    const float* ln1_g    = (const float*)d_in[10];
    const float* ln1_b    = (const float*)d_in[11];
    const float* W1       = (const float*)d_in[12];
    const float* b1       = (const float*)d_in[13];
    const float* W2       = (const float*)d_in[14];
    const float* b2       = (const float*)d_in[15];
    const float* ln2_g    = (const float*)d_in[16];
    const float* ln2_b    = (const float*)d_in[17];
    const float* lnf_g    = (const float*)d_in[18];
    const float* lnf_b    = (const float*)d_in[19];

    int L, with_mask;
    if (out_size % (BB * (DM + 1)) == 0) { L = out_size / (BB * (DM + 1)); with_mask = 1; }
    else                                 { L = out_size / (BB * DM);        with_mask = 0; }
    const int M = BB * L;

    float *x, *q, *k, *v, *ao, *y, *hbuf;
    cudaGetSymbolAddress((void**)&x,    g_x);
    cudaGetSymbolAddress((void**)&q,    g_q);
    cudaGetSymbolAddress((void**)&k,    g_k);
    cudaGetSymbolAddress((void**)&v,    g_v);
    cudaGetSymbolAddress((void**)&ao,   g_ao);
    cudaGetSymbolAddress((void**)&y,    g_y);
    cudaGetSymbolAddress((void**)&hbuf, g_h);

    pack_kernel<<<1, 64>>>(npl, ttn, L);
    embed_ln_kernel<<<M, 128>>>(poi_type, loc_emb, emb, lnf_g, lnf_b, L);

    dim3 g512((DM + 127) / 128, (M + 127) / 128);
    dim3 g2048((DI + 127) / 128, (M + 127) / 128);
    dim3 gattn(BB, NH);

    for (int l = 0; l < NLAY; l++) {
        const float* wq = Wq + (size_t)l * DM * DM;
        const float* wk = Wk + (size_t)l * DM * DM;
        const float* wv = Wv + (size_t)l * DM * DM;
        const float* wo = Wo + (size_t)l * DM * DM;
        const float* w1 = W1 + (size_t)l * DM * DI;
        const float* w2 = W2 + (size_t)l * DI * DM;

        mma_gemm_kernel<<<g512, 256>>>(x, wq, nullptr, q, M, DM, DM, 0);
        mma_gemm_kernel<<<g512, 256>>>(x, wk, nullptr, k, M, DM, DM, 0);
        mma_gemm_kernel<<<g512, 256>>>(x, wv, nullptr, v, M, DM, DM, 0);
        attn_kernel<<<gattn, 256>>>(q, k, v, ao, L);
        mma_gemm_kernel<<<g512, 256>>>(ao, wo, bo + (size_t)l * DM, y, M, DM, DM, 0);
        resid_ln_kernel<<<M, 128>>>(x, y, ln1_g + (size_t)l * DM, ln1_b + (size_t)l * DM);
        mma_gemm_kernel<<<g2048, 256>>>(x, w1, b1 + (size_t)l * DI, hbuf, M, DI, DM, 1);
        mma_gemm_kernel<<<g512, 256>>>(hbuf, w2, b2 + (size_t)l * DM, y, M, DM, DI, 0);
        resid_ln_kernel<<<M, 128>>>(x, y, ln2_g + (size_t)l * DM, ln2_b + (size_t)l * DM);
    }

    int n_out = BB * L * DM + (with_mask ? BB * L : 0);
    writeout_kernel<<<(n_out + 255) / 256, 256>>>((float*)d_out, L, with_mask);
}

// round 5
// speedup vs baseline: 2.9338x; 1.3595x over previous
#include <cuda_runtime.h>
#include <math.h>
#include <stdint.h>

// ---------------- problem constants ----------------
#define BB   64
#define DM   512
#define NH   8
#define DKH  64
#define DI   2048
#define NLAY 4
#define SS   12
#define REP_IDX 1
#define LMAX 385
#define LPAD 392

// ---------------- scratch ----------------
__device__ int   g_seq_len[BB];
__device__ int   g_poi_idx[BB * LMAX];
__device__ int   g_tok_idx[BB * LMAX];
__device__ float g_x [BB * LMAX * DM];
__device__ float g_q [BB * LMAX * DM];
__device__ float g_k [BB * LMAX * DM];
__device__ float g_v [BB * LMAX * DM];
__device__ float g_ao[BB * LMAX * DM];
__device__ float g_y [BB * LMAX * DM];
__device__ float g_h [BB * LMAX * DI];

// ---------------- pack ----------------
__global__ void pack_kernel(const int* __restrict__ npl,
                            const int* __restrict__ ttn, int L) {
    int b = threadIdx.x;
    if (b >= BB) return;
    int start = 0;
    for (int i = 0; i < b; i++) start += npl[i];
    int end = start + npl[b];
    int pos = 1;
    for (int p = start; p < end; p++) {
        int t = ttn[p];
        for (int u = 0; u < t && pos < L; u++) {
            g_poi_idx[b * L + pos] = p;
            g_tok_idx[b * L + pos] = u;
            pos++;
        }
    }
    g_seq_len[b] = pos;
}

// ---------------- block reduce (128 threads) ----------------
__device__ __forceinline__ void block_reduce2_128(float& s, float& sq) {
    #pragma unroll
    for (int o = 16; o > 0; o >>= 1) {
        s  += __shfl_xor_sync(0xFFFFFFFFu, s,  o);
        sq += __shfl_xor_sync(0xFFFFFFFFu, sq, o);
    }
    __shared__ float rs[4], rq[4];
    int w = threadIdx.x >> 5, ln = threadIdx.x & 31;
    if (ln == 0) { rs[w] = s; rq[w] = sq; }
    __syncthreads();
    s  = rs[0] + rs[1] + rs[2] + rs[3];
    sq = rq[0] + rq[1] + rq[2] + rq[3];
}

__device__ __forceinline__ float postab(int t, int d) {
    int i2 = d & ~1;
    float f = powf(10000.0f, -(float)i2 / (float)DM);
    float ang = (float)t * f;
    return (d & 1) ? cosf(ang) : sinf(ang);
}

// ---------------- embed + final LN ----------------
__global__ __launch_bounds__(128) void embed_ln_kernel(
    const int* __restrict__ poi_type, const float* __restrict__ loc_emb,
    const float* __restrict__ emb, const float* __restrict__ lnf_g,
    const float* __restrict__ lnf_b, int L) {
    int row = blockIdx.x;
    int b = row / L, l = row - b * L;
    int tid = threadIdx.x;
    int d0 = tid * 4;
    float v[4];
    int sl = g_seq_len[b];
    if (l == 0) {
        #pragma unroll
        for (int i = 0; i < 4; i++) v[i] = emb[REP_IDX * DM + d0 + i];
    } else if (l < sl) {
        int p = g_poi_idx[b * L + l];
        int t = g_tok_idx[b * L + l];
        int tok = poi_type[p * SS + t];
        #pragma unroll
        for (int i = 0; i < 4; i++) {
            int d = d0 + i;
            v[i] = emb[tok * DM + d] + postab(t, d) + loc_emb[p * DM + d];
        }
    } else {
        #pragma unroll
        for (int i = 0; i < 4; i++) v[i] = 0.0f;
    }
    float s = v[0] + v[1] + v[2] + v[3];
    float sq = v[0]*v[0] + v[1]*v[1] + v[2]*v[2] + v[3]*v[3];
    block_reduce2_128(s, sq);
    float mean = s * (1.0f / DM);
    float var  = sq * (1.0f / DM) - mean * mean;
    float r = rsqrtf(var + 1e-6f);
    float4 o;
    o.x = lnf_g[d0+0] * (v[0]-mean) * r + lnf_b[d0+0];
    o.y = lnf_g[d0+1] * (v[1]-mean) * r + lnf_b[d0+1];
    o.z = lnf_g[d0+2] * (v[2]-mean) * r + lnf_b[d0+2];
    o.w = lnf_g[d0+3] * (v[3]-mean) * r + lnf_b[d0+3];
    *(float4*)(g_x + (size_t)row * DM + d0) = o;
}

// ---------------- residual + LN ----------------
__global__ __launch_bounds__(128) void resid_ln_kernel(
    float* __restrict__ x, const float* __restrict__ y,
    const float* __restrict__ g, const float* __restrict__ bb) {
    size_t base = (size_t)blockIdx.x * DM + threadIdx.x * 4;
    float4 xv = *(float4*)(x + base);
    float4 yv = *(const float4*)(y + base);
    float v[4] = { xv.x + yv.x, xv.y + yv.y, xv.z + yv.z, xv.w + yv.w };
    float s = v[0] + v[1] + v[2] + v[3];
    float sq = v[0]*v[0] + v[1]*v[1] + v[2]*v[2] + v[3]*v[3];
    block_reduce2_128(s, sq);
    float mean = s * (1.0f / DM);
    float var  = sq * (1.0f / DM) - mean * mean;
    float r = rsqrtf(var + 1e-6f);
    int d0 = threadIdx.x * 4;
    float4 o;
    o.x = g[d0+0] * (v[0]-mean) * r + bb[d0+0];
    o.y = g[d0+1] * (v[1]-mean) * r + bb[d0+1];
    o.z = g[d0+2] * (v[2]-mean) * r + bb[d0+2];
    o.w = g[d0+3] * (v[3]-mean) * r + bb[d0+3];
    *(float4*)(x + base) = o;
}

// ---------------- tf32 helpers ----------------
__device__ __forceinline__ float f2tf(float x) {
    uint32_t u;
    asm("cvt.rna.tf32.f32 %0, %1;" : "=r"(u) : "f"(x));
    return __uint_as_float(u);
}

__device__ __forceinline__ void mma1688(float* c, const uint32_t* a, const uint32_t* b) {
    asm volatile(
        "mma.sync.aligned.m16n8k8.row.col.f32.tf32.tf32.f32 "
        "{%0,%1,%2,%3}, {%4,%5,%6,%7}, {%8,%9}, {%0,%1,%2,%3};"
        : "+f"(c[0]), "+f"(c[1]), "+f"(c[2]), "+f"(c[3])
        : "r"(a[0]), "r"(a[1]), "r"(a[2]), "r"(a[3]),
          "r"(b[0]), "r"(b[1]));
}

// ---------------- tf32 tensor-core GEMM ----------------
// 128x128 block, BK=16 double-buffered, 8 warps in 2x4 grid, warp tile 64x32.
#define GSTR 136
__global__ __launch_bounds__(256, 2) void mma_gemm_kernel(
    const float* __restrict__ A, const float* __restrict__ W,
    const float* __restrict__ bias, float* __restrict__ C,
    int M, int N, int K, int do_relu) {
    __shared__ float As[2][16][GSTR];
    __shared__ float Bs[2][16][GSTR];
    const int tid  = threadIdx.x;
    const int wid  = tid >> 5, lane = tid & 31;
    const int wm   = (wid & 1) * 64;
    const int wn   = (wid >> 1) * 32;
    const int row0 = blockIdx.y * 128, col0 = blockIdx.x * 128;

    const int a_row = tid >> 1, a_k = (tid & 1) * 8;
    const int b_k   = tid >> 5, b_n = (tid & 31) * 4;

    float acc[4][4][4];
    #pragma unroll
    for (int mt = 0; mt < 4; mt++)
        #pragma unroll
        for (int nt = 0; nt < 4; nt++)
            #pragma unroll
            for (int i = 0; i < 4; i++) acc[mt][nt][i] = 0.0f;

    float4 sa0, sa1, sb0, sb1;

    auto gload = [&](int k0) {
        int gr = row0 + a_row;
        if (gr < M) {
            const float* ap = A + (size_t)gr * K + k0 + a_k;
            sa0 = *(const float4*)(ap);
            sa1 = *(const float4*)(ap + 4);
        } else {
            sa0 = make_float4(0.f,0.f,0.f,0.f);
            sa1 = sa0;
        }
        sb0 = *(const float4*)(W + (size_t)(k0 + b_k)     * N + col0 + b_n);
        sb1 = *(const float4*)(W + (size_t)(k0 + b_k + 8) * N + col0 + b_n);
    };
    auto sstore = [&](int bf) {
        As[bf][a_k+0][a_row] = f2tf(sa0.x);
        As[bf][a_k+1][a_row] = f2tf(sa0.y);
        As[bf][a_k+2][a_row] = f2tf(sa0.z);
        As[bf][a_k+3][a_row] = f2tf(sa0.w);
        As[bf][a_k+4][a_row] = f2tf(sa1.x);
        As[bf][a_k+5][a_row] = f2tf(sa1.y);
        As[bf][a_k+6][a_row] = f2tf(sa1.z);
        As[bf][a_k+7][a_row] = f2tf(sa1.w);
        Bs[bf][b_k][b_n+0] = f2tf(sb0.x);
        Bs[bf][b_k][b_n+1] = f2tf(sb0.y);
        Bs[bf][b_k][b_n+2] = f2tf(sb0.z);
        Bs[bf][b_k][b_n+3] = f2tf(sb0.w);
        Bs[bf][b_k+8][b_n+0] = f2tf(sb1.x);
        Bs[bf][b_k+8][b_n+1] = f2tf(sb1.y);
        Bs[bf][b_k+8][b_n+2] = f2tf(sb1.z);
        Bs[bf][b_k+8][b_n+3] = f2tf(sb1.w);
    };

    gload(0);
    sstore(0);
    __syncthreads();

    const int r = lane >> 2, c = lane & 3;
    int buf = 0;
    for (int k0 = 0; k0 < K; k0 += 16) {
        bool nxt = (k0 + 16) < K;
        if (nxt) gload(k0 + 16);
        #pragma unroll
        for (int ks = 0; ks < 16; ks += 8) {
            uint32_t af[4][4], bfr[4][2];
            #pragma unroll
            for (int mt = 0; mt < 4; mt++) {
                int mb = wm + mt * 16 + r;
                af[mt][0] = __float_as_uint(As[buf][ks + c    ][mb    ]);
                af[mt][1] = __float_as_uint(As[buf][ks + c    ][mb + 8]);
                af[mt][2] = __float_as_uint(As[buf][ks + c + 4][mb    ]);
                af[mt][3] = __float_as_uint(As[buf][ks + c + 4][mb + 8]);
            }
            #pragma unroll
            for (int nt = 0; nt < 4; nt++) {
                int nb = wn + nt * 8 + r;
                bfr[nt][0] = __float_as_uint(Bs[buf][ks + c    ][nb]);
                bfr[nt][1] = __float_as_uint(Bs[buf][ks + c + 4][nb]);
            }
            #pragma unroll
            for (int mt = 0; mt < 4; mt++)
                #pragma unroll
                for (int nt = 0; nt < 4; nt++)
                    mma1688(acc[mt][nt], af[mt], bfr[nt]);
        }
        if (nxt) sstore(buf ^ 1);
        __syncthreads();
        buf ^= 1;
    }

    #pragma unroll
    for (int mt = 0; mt < 4; mt++) {
        int rrow = row0 + wm + mt * 16 + (lane >> 2);
        #pragma unroll
        for (int nt = 0; nt < 4; nt++) {
            int ccol = col0 + wn + nt * 8 + (lane & 3) * 2;
            float2 v0 = make_float2(acc[mt][nt][0], acc[mt][nt][1]);
            float2 v1 = make_float2(acc[mt][nt][2], acc[mt][nt][3]);
            if (bias) {
                float b0 = bias[ccol], b1 = bias[ccol + 1];
                v0.x += b0; v0.y += b1;
                v1.x += b0; v1.y += b1;
            }
            if (do_relu) {
                v0.x = fmaxf(v0.x, 0.f); v0.y = fmaxf(v0.y, 0.f);
                v1.x = fmaxf(v1.x, 0.f); v1.y = fmaxf(v1.y, 0.f);
            }
            if (rrow < M)     *(float2*)(C + (size_t)rrow     * N + ccol) = v0;
            if (rrow + 8 < M) *(float2*)(C + (size_t)(rrow+8) * N + ccol) = v1;
        }
    }
}

// ---------------- attention v2 ----------------
// Block per (b,h). Full K head slice staged once in dynamic smem (72-word row
// stride, 32-dim halves at offsets 0 and 36 -> conflict-free). Each warp
// processes 2 queries; dims split across lane pairs, combined via shfl_xor(1).
#define KSTRW 72
__global__ __launch_bounds__(256) void attn_kernel(
    const float* __restrict__ Q, const float* __restrict__ K,
    const float* __restrict__ V, float* __restrict__ O, int L) {
    extern __shared__ float kt[];       // [L][KSTRW]
    __shared__ float sc[16][LPAD];
    int b = blockIdx.x, h = blockIdx.y;
    int tid = threadIdx.x;
    int w = tid >> 5, lane = tid & 31;
    int half = lane & 1, jj = lane >> 1;
    int sl = g_seq_len[b];
    size_t base = ((size_t)b * L) * DM + h * DKH;

    // stage K once
    for (int idx = tid; idx < L * 16; idx += 256) {
        int rr = idx >> 4, cc = idx & 15;
        float4 kv = *(const float4*)(K + base + (size_t)rr * DM + cc * 4);
        int off = (cc < 8) ? cc * 4 : (36 + (cc - 8) * 4);
        *(float4*)&kt[rr * KSTRW + off] = kv;
    }
    __syncthreads();

    const int ntile = (L + 15) / 16;
    for (int i0 = w * 2; i0 < L; i0 += 16) {
        int i1 = i0 + 1;
        bool has1 = (i1 < L);
        // q halves in registers: 8 float4 per query
        float4 qa[8], qb[8];
        {
            const float4* q0p = (const float4*)(Q + base + (size_t)i0 * DM + half * 32);
            #pragma unroll
            for (int d = 0; d < 8; d++) qa[d] = q0p[d];
            if (has1) {
                const float4* q1p = (const float4*)(Q + base + (size_t)i1 * DM + half * 32);
                #pragma unroll
                for (int d = 0; d < 8; d++) qb[d] = q1p[d];
            } else {
                #pragma unroll
                for (int d = 0; d < 8; d++) qb[d] = make_float4(0.f,0.f,0.f,0.f);
            }
        }
        // scores + running max (lane tracks the row matching its parity)
        float mval = -3.0e38f;
        for (int t = 0; t < ntile; t++) {
            int jt = t * 16 + jj;
            bool valid = (jt < sl);
            float d0 = 0.f, d1 = 0.f;
            if (valid) {
                const float4* kp = (const float4*)&kt[jt * KSTRW + half * 36];
                #pragma unroll
                for (int d = 0; d < 8; d++) {
                    float4 kv = kp[d];
                    d0 += qa[d].x*kv.x + qa[d].y*kv.y + qa[d].z*kv.z + qa[d].w*kv.w;
                    d1 += qb[d].x*kv.x + qb[d].y*kv.y + qb[d].z*kv.z + qb[d].w*kv.w;
                }
            }
            d0 += __shfl_xor_sync(0xFFFFFFFFu, d0, 1);
            d1 += __shfl_xor_sync(0xFFFFFFFFu, d1, 1);
            float s0 = valid ? d0 * 0.125f : -1e9f;
            float s1 = valid ? d1 * 0.125f : -1e9f;
            if (jt < L) {
                if (half == 0) { sc[2*w  ][jt] = s0; mval = fmaxf(mval, s0); }
                else           { sc[2*w+1][jt] = s1; mval = fmaxf(mval, s1); }
            }
        }
        // reduce max within parity group (offsets 2,4,8,16 preserve parity)
        #pragma unroll
        for (int o = 2; o <= 16; o <<= 1)
            mval = fmaxf(mval, __shfl_xor_sync(0xFFFFFFFFu, mval, o));
        // exp + sum (each parity group handles its own row)
        float sum = 0.f;
        int myrow = 2 * w + half;
        for (int t = 0; t < ntile; t++) {
            int jt = t * 16 + jj;
            if (jt < L) {
                float e = expf(sc[myrow][jt] - mval);
                sc[myrow][jt] = e;
                sum += e;
            }
        }
        #pragma unroll
        for (int o = 2; o <= 16; o <<= 1)
            sum += __shfl_xor_sync(0xFFFFFFFFu, sum, o);
        float inv = 1.0f / sum;
        float inv0 = __shfl_sync(0xFFFFFFFFu, inv, 0);
        float inv1 = __shfl_sync(0xFFFFFFFFu, inv, 1);
        __syncwarp();
        // PV: lane owns dims (2*lane, 2*lane+1) for both queries
        float ax0 = 0.f, ay0 = 0.f, ax1 = 0.f, ay1 = 0.f;
        const float* vp = V + base + 2 * lane;
        #pragma unroll 4
        for (int j = 0; j < L; j++) {
            float2 vv = *(const float2*)(vp + (size_t)j * DM);
            float p0 = sc[2*w  ][j];
            float p1 = sc[2*w+1][j];
            ax0 += p0 * vv.x; ay0 += p0 * vv.y;
            ax1 += p1 * vv.x; ay1 += p1 * vv.y;
        }
        *(float2*)(O + base + (size_t)i0 * DM + 2 * lane) =
            make_float2(ax0 * inv0, ay0 * inv0);
        if (has1)
            *(float2*)(O + base + (size_t)i1 * DM + 2 * lane) =
                make_float2(ax1 * inv1, ay1 * inv1);
        __syncwarp();
    }
}

// ---------------- writeout ----------------
__global__ void writeout_kernel(float* __restrict__ out, int L, int with_mask) {
    int idx = blockIdx.x * blockDim.x + threadIdx.x;
    int total = BB * L * DM;
    if (idx < total) out[idx] = g_x[idx];
    if (with_mask && idx < BB * L) {
        int b = idx / L, l = idx - b * L;
        out[total + idx] = (l < g_seq_len[b]) ? 1.0f : 0.0f;
    }
}

// ---------------- host launcher ----------------
extern "C" void kernel_launch(void* const* d_in, const int* in_sizes, int n_in,
                              void* d_out, int out_size) {
    const int*   poi_type = (const int*)  d_in[0];
    const float* loc_emb  = (const float*)d_in[1];
    const int*   npl      = (const int*)  d_in[2];
    const int*   ttn      = (const int*)  d_in[3];
    const float* emb      = (const float*)d_in[4];
    const float* Wq       = (const float*)d_in[5];
    const float* Wk       = (const float*)d_in[6];
    const float* Wv       = (const float*)d_in[7];
    const float* Wo       = (const float*)d_in[8];
    const float* bo       = (const float*)d_in[9];
    const float* ln1_g    = (const float*)d_in[10];
    const float* ln1_b    = (const float*)d_in[11];
    const float* W1       = (const float*)d_in[12];
    const float* b1       = (const float*)d_in[13];
    const float* W2       = (const float*)d_in[14];
    const float* b2       = (const float*)d_in[15];
    const float* ln2_g    = (const float*)d_in[16];
    const float* ln2_b    = (const float*)d_in[17];
    const float* lnf_g    = (const float*)d_in[18];
    const float* lnf_b    = (const float*)d_in[19];

    int L, with_mask;
    if (out_size % (BB * (DM + 1)) == 0) { L = out_size / (BB * (DM + 1)); with_mask = 1; }
    else                                 { L = out_size / (BB * DM);        with_mask = 0; }
    const int M = BB * L;

    float *x, *q, *k, *v, *ao, *y, *hbuf;
    cudaGetSymbolAddress((void**)&x,    g_x);
    cudaGetSymbolAddress((void**)&q,    g_q);
    cudaGetSymbolAddress((void**)&k,    g_k);
    cudaGetSymbolAddress((void**)&v,    g_v);
    cudaGetSymbolAddress((void**)&ao,   g_ao);
    cudaGetSymbolAddress((void**)&y,    g_y);
    cudaGetSymbolAddress((void**)&hbuf, g_h);

    int attn_smem = L * KSTRW * 4;
    cudaFuncSetAttribute(attn_kernel,
                         cudaFuncAttributeMaxDynamicSharedMemorySize,
                         LMAX * KSTRW * 4);

    pack_kernel<<<1, 64>>>(npl, ttn, L);
    embed_ln_kernel<<<M, 128>>>(poi_type, loc_emb, emb, lnf_g, lnf_b, L);

    dim3 g512((DM + 127) / 128, (M + 127) / 128);
    dim3 g2048((DI + 127) / 128, (M + 127) / 128);
    dim3 gattn(BB, NH);

    for (int l = 0; l < NLAY; l++) {
        const float* wq = Wq + (size_t)l * DM * DM;
        const float* wk = Wk + (size_t)l * DM * DM;
        const float* wv = Wv + (size_t)l * DM * DM;
        const float* wo = Wo + (size_t)l * DM * DM;
        const float* w1 = W1 + (size_t)l * DM * DI;
        const float* w2 = W2 + (size_t)l * DI * DM;

        mma_gemm_kernel<<<g512, 256>>>(x, wq, nullptr, q, M, DM, DM, 0);
        mma_gemm_kernel<<<g512, 256>>>(x, wk, nullptr, k, M, DM, DM, 0);
        mma_gemm_kernel<<<g512, 256>>>(x, wv, nullptr, v, M, DM, DM, 0);
        attn_kernel<<<gattn, 256, attn_smem>>>(q, k, v, ao, L);
        mma_gemm_kernel<<<g512, 256>>>(ao, wo, bo + (size_t)l * DM, y, M, DM, DM, 0);
        resid_ln_kernel<<<M, 128>>>(x, y, ln1_g + (size_t)l * DM, ln1_b + (size_t)l * DM);
        mma_gemm_kernel<<<g2048, 256>>>(x, w1, b1 + (size_t)l * DI, hbuf, M, DI, DM, 1);
        mma_gemm_kernel<<<g512, 256>>>(hbuf, w2, b2 + (size_t)l * DM, y, M, DM, DI, 0);
        resid_ln_kernel<<<M, 128>>>(x, y, ln2_g + (size_t)l * DM, ln2_b + (size_t)l * DM);
    }

    int n_out = BB * L * DM + (with_mask ? BB * L : 0);
    writeout_kernel<<<(n_out + 255) / 256, 256>>>((float*)d_out, L, with_mask);
}